// round 8
// baseline (speedup 1.0000x reference)
#include <cuda_runtime.h>
#include <cstdint>
#include <cstddef>

// Bihomogeneous_k3 — warp-per-row, fused re+im, phase-aligned stores,
// 2 columns per lane: p-chain amortized, vectorized STG.64 re-stores.

#define NVAR 5
#define NM 35
#define NPAIR 630
#define NCOL 1225
#define WPB 8
#define NGRP2 10     // 10 groups x 64 columns cover [c0, c0+640) >= 630

__host__ __device__ constexpr int off_of(int p) { return p * (71 - p) / 2; }
__host__ __device__ constexpr int p_of(int s) {
    int p = 0;
    while (off_of(p + 1) <= s) p++;
    return p;
}
__host__ __device__ constexpr int cmin(int a, int b) { return a < b ? a : b; }

template<int... I> struct iseq {};
template<int N, int... I> struct make_iseq : make_iseq<N - 1, N - 1, I...> {};
template<int... I> struct make_iseq<0, I...> { using type = iseq<I...>; };

// fold: p and qoff = p - off(p) via predicated adds against compile-time
// breakpoints. Passing breakpoint P adds +1 to p and +(P-35) to qoff.
template<int PMIN, int... J>
__device__ __forceinline__ void pq_chain(int s, int& p, int& qoff, iseq<J...>) {
    p = PMIN;
    qoff = PMIN - off_of(PMIN);
    (([&] {
        constexpr int P = PMIN + 1 + J;
        const bool c = s >= off_of(P);
        p += c ? 1 : 0;
        qoff += c ? (P - 35) : 0;
    }()), ...);
}

template<int G>
__device__ __forceinline__ void do_group(const float2* __restrict__ zz,
                                         float* __restrict__ orow,
                                         float* __restrict__ orowi,
                                         int c0, int lane) {
    const int s0 = c0 + 64 * G + 2 * lane;
    constexpr bool guard = (64 * G + 93 >= NPAIR);
    if constexpr (guard) {
        if (s0 >= NPAIR) return;
    }
    constexpr int pmin = p_of(64 * G);
    constexpr int pmax = p_of(cmin(64 * G + 93, NPAIR - 1));

    int p, qoff;
    pq_chain<pmin>(s0, p, qoff, typename make_iseq<pmax - pmin>::type{});
    const int  q0 = s0 + qoff;
    const bool d  = (q0 == 34);            // next column is a diagonal pair
    const int  p1 = p + (d ? 1 : 0);
    const int  q1 = d ? p1 : q0 + 1;

    const float2 a0 = zz[p];               // broadcast
    const float2 b0 = zz[q0];
    const float2 a1 = zz[p1];              // == a0 except at run boundary
    const float2 b1 = zz[q1];

    const float r0 = a0.x * b0.x + a0.y * b0.y;
    const float r1 = a1.x * b1.x + a1.y * b1.y;

    bool have1 = true;
    if constexpr (guard) have1 = (s0 + 1 < NPAIR);

    if (have1)
        __stcs(reinterpret_cast<float2*>(orow + s0), make_float2(r0, r1)); // aligned STG.64
    else
        __stcs(orow + s0, r0);

    if (q0 > p)                                       // strict -> im column
        __stcs(orowi + (s0 - p), a0.y * b0.x - a0.x * b0.y);
    if (!d && have1)                                  // p1 == p here
        __stcs(orowi + (s0 + 1 - p), a1.y * b1.x - a1.x * b1.y);
}

template<int... G>
__device__ __forceinline__ void all_groups(iseq<G...>, const float2* __restrict__ zz,
                                           float* __restrict__ orow,
                                           float* __restrict__ orowi,
                                           int c0, int lane) {
    (do_group<G>(zz, orow, orowi, c0, lane), ...);
}

// monomial index table for stage 1 (2 warp-iterations, negligible traffic)
struct TabM { ushort ijk[40]; };
static constexpr TabM make_tabm() {
    TabM t{};
    int m = 0;
    for (int i = 0; i < NVAR; i++)
        for (int j = i; j < NVAR; j++)
            for (int k = j; k < NVAR; k++) {
                t.ijk[m] = (ushort)(i | (j << 4) | (k << 8));
                m++;
            }
    return t;
}
__device__ const TabM g_tabm = make_tabm();

__global__ void __launch_bounds__(WPB * 32)
bihom_k3_kernel(const float* __restrict__ z_re,
                const float* __restrict__ z_im,
                float* __restrict__ out, int B)
{
    const int warp = threadIdx.x >> 5;
    const int lane = threadIdx.x & 31;
    const int row  = blockIdx.x * WPB + warp;

    __shared__ float2 szz[WPB][NM + 1];    // index 35 = safe pad for boundary
    __shared__ float  sz[WPB][2][NVAR + 3];

    if (row >= B) return;   // one row per warp: uniform exit

    // stage 0: row inputs into smem
    if (lane < NVAR) {
        sz[warp][0][lane] = z_re[row * NVAR + lane];
        sz[warp][1][lane] = z_im[row * NVAR + lane];
    }
    __syncwarp();

    // stage 1: 35 complex monomials z_i z_j z_k  (+ zero the pad)
    for (int mm = lane; mm < NM; mm += 32) {
        const unsigned v = g_tabm.ijk[mm];
        const int i = v & 15, j = (v >> 4) & 15, k = (v >> 8) & 15;
        const float ar = sz[warp][0][i], ai = sz[warp][1][i];
        const float br = sz[warp][0][j], bi = sz[warp][1][j];
        const float cr = sz[warp][0][k], ci = sz[warp][1][k];
        const float tr = ar * br - ai * bi;
        const float ti = ar * bi + ai * br;
        szz[warp][mm] = make_float2(tr * cr - ti * ci, tr * ci + ti * cr);
    }
    if (lane == 0) szz[warp][NM] = make_float2(0.f, 0.f);
    __syncwarp();

    // stage 2: phase so that (row*NCOL + c0) is 128B-aligned
    const int rowoff = row * NCOL;
    const int c0 = (-rowoff) & 31;

    float* __restrict__ orow  = out + (size_t)rowoff;
    float* __restrict__ orowi = orow + (NPAIR - 1);   // im col = 629 + s - p
    const float2* zz = szz[warp];

    // prologue: columns [0, c0). Here s < 31 < off(1)=35 -> p = 0, q = s.
    {
        const int s0 = c0 - 32 + lane;
        if (s0 >= 0) {
            const float2 a = zz[0];
            const float2 b = zz[s0];
            __stcs(orow + s0, a.x * b.x + a.y * b.y);
            if (s0 > 0)
                __stcs(orowi + s0, a.y * b.x - a.x * b.y);
        }
    }

    all_groups(typename make_iseq<NGRP2>::type{}, zz, orow, orowi, c0, lane);
}

extern "C" void kernel_launch(void* const* d_in, const int* in_sizes, int n_in,
                              void* d_out, int out_size) {
    const float* z_re = (const float*)d_in[0];
    const float* z_im = (const float*)d_in[1];
    float* out = (float*)d_out;
    const int B = in_sizes[0] / NVAR;
    const int grid = (B + WPB - 1) / WPB;
    bihom_k3_kernel<<<grid, WPB * 32>>>(z_re, z_im, out, B);
}

// round 9
// speedup vs baseline: 1.2637x; 1.2637x over previous
#include <cuda_runtime.h>
#include <cstdint>
#include <cstddef>

// Bihomogeneous_k3 — warp-per-row, fused re+im, phase-aligned re-stores,
// stride-1 lane mapping (R6 memory pattern, byte-identical), with
// loop-invariant hoisting: immediate-offset breakpoint tests and stores,
// predicated-add chain producing both p and qoff (no per-group IMAD/SHF).

#define NVAR 5
#define NM 35
#define NPAIR 630
#define NCOL 1225
#define WPB 8
#define NGRP 20

__host__ __device__ constexpr int off_of(int p) { return p * (71 - p) / 2; }
__host__ __device__ constexpr int p_of(int s) {
    int p = 0;
    while (off_of(p + 1) <= s) p++;
    return p;
}
__host__ __device__ constexpr int cmin(int a, int b) { return a < b ? a : b; }

template<int... I> struct iseq {};
template<int N, int... I> struct make_iseq : make_iseq<N - 1, N - 1, I...> {};
template<int... I> struct make_iseq<0, I...> { using type = iseq<I...>; };

// chain: p and qoff = p - off(p) via predicated adds; thresholds are
// immediates (off(P) - SB), compared against loop-invariant Lc.
template<int SB, int PMIN, int... J>
__device__ __forceinline__ void pq_chain(int Lc, int& p, int& qoff, iseq<J...>) {
    p = PMIN;
    qoff = PMIN - off_of(PMIN);
    (([&] {
        constexpr int P = PMIN + 1 + J;
        const bool c = Lc >= (off_of(P) - SB);
        p += c ? 1 : 0;
        qoff += c ? (P - 35) : 0;     // off(P)-off(P-1) = 35-P, so qoff += P-35... 
    }()), ...);
}

template<int G>
__device__ __forceinline__ void do_group(const float2* __restrict__ zz,
                                         float* __restrict__ base_re,
                                         float* __restrict__ base_im,
                                         int Lc) {
    constexpr int SB = 32 * G;
    if constexpr (SB + 62 >= NPAIR) {       // Lc <= 62
        if (Lc + SB >= NPAIR) return;
    }
    constexpr int pmin = p_of(SB);
    constexpr int pmax = p_of(cmin(SB + 62, NPAIR - 1));

    int p, qoff;
    pq_chain<SB, pmin>(Lc, p, qoff, typename make_iseq<pmax - pmin>::type{});
    const int q = Lc + (SB + qoff);         // s + p - off(p)

    const float2 a = zz[p];                 // broadcast: 1 wf
    const float2 b = zz[q];                 // consecutive q: 2 wf
    __stcs(base_re + SB, a.x * b.x + a.y * b.y);   // imm offset, aligned: 1 wf
    if (q > p)                              // strict pair -> im column
        __stcs(base_im + (SB - p), a.y * b.x - a.x * b.y);
}

template<int... G>
__device__ __forceinline__ void all_groups(iseq<G...>, const float2* __restrict__ zz,
                                           float* __restrict__ base_re,
                                           float* __restrict__ base_im, int Lc) {
    (do_group<G>(zz, base_re, base_im, Lc), ...);
}

// monomial index table for stage 1 (2 warp-iterations, negligible traffic)
struct TabM { ushort ijk[40]; };
static constexpr TabM make_tabm() {
    TabM t{};
    int m = 0;
    for (int i = 0; i < NVAR; i++)
        for (int j = i; j < NVAR; j++)
            for (int k = j; k < NVAR; k++) {
                t.ijk[m] = (ushort)(i | (j << 4) | (k << 8));
                m++;
            }
    return t;
}
__device__ const TabM g_tabm = make_tabm();

__global__ void __launch_bounds__(WPB * 32)
bihom_k3_kernel(const float* __restrict__ z_re,
                const float* __restrict__ z_im,
                float* __restrict__ out, int B)
{
    const int warp = threadIdx.x >> 5;
    const int lane = threadIdx.x & 31;
    const int row  = blockIdx.x * WPB + warp;

    __shared__ float2 szz[WPB][NM + 1];
    __shared__ float  sz[WPB][2][NVAR + 3];

    if (row >= B) return;   // one row per warp: uniform exit

    // stage 0: row inputs into smem
    if (lane < NVAR) {
        sz[warp][0][lane] = z_re[row * NVAR + lane];
        sz[warp][1][lane] = z_im[row * NVAR + lane];
    }
    __syncwarp();

    // stage 1: 35 complex monomials z_i z_j z_k
    for (int mm = lane; mm < NM; mm += 32) {
        const unsigned v = g_tabm.ijk[mm];
        const int i = v & 15, j = (v >> 4) & 15, k = (v >> 8) & 15;
        const float ar = sz[warp][0][i], ai = sz[warp][1][i];
        const float br = sz[warp][0][j], bi = sz[warp][1][j];
        const float cr = sz[warp][0][k], ci = sz[warp][1][k];
        const float tr = ar * br - ai * bi;
        const float ti = ar * bi + ai * br;
        szz[warp][mm] = make_float2(tr * cr - ti * ci, tr * ci + ti * cr);
    }
    __syncwarp();

    // stage 2: phase so that (row*NCOL + c0) is 128B-aligned
    const int rowoff = row * NCOL;
    const int c0 = (-rowoff) & 31;
    const int Lc = c0 + lane;                        // loop-invariant

    float* __restrict__ orow  = out + (size_t)rowoff;
    float* __restrict__ orowi = orow + (NPAIR - 1);  // im col = 629 + s - p
    float* __restrict__ base_re = orow + Lc;         // s = Lc + SB
    float* __restrict__ base_im = orowi + Lc;
    const float2* zz = szz[warp];

    // prologue: columns [0, c0). Here s < 31 < off(1)=35 -> p = 0, q = s.
    {
        const int s0 = c0 - 32 + lane;
        if (s0 >= 0) {
            const float2 a = zz[0];
            const float2 b = zz[s0];
            __stcs(orow + s0, a.x * b.x + a.y * b.y);
            if (s0 > 0)
                __stcs(orowi + s0, a.y * b.x - a.x * b.y);
        }
    }

    all_groups(typename make_iseq<NGRP>::type{}, zz, base_re, base_im, Lc);
}

extern "C" void kernel_launch(void* const* d_in, const int* in_sizes, int n_in,
                              void* d_out, int out_size) {
    const float* z_re = (const float*)d_in[0];
    const float* z_im = (const float*)d_in[1];
    float* out = (float*)d_out;
    const int B = in_sizes[0] / NVAR;
    const int grid = (B + WPB - 1) / WPB;
    bihom_k3_kernel<<<grid, WPB * 32>>>(z_re, z_im, out, B);
}